// round 5
// baseline (speedup 1.0000x reference)
#include <cuda_runtime.h>
#include <stdint.h>

// Problem constants
#define F0C   39
#define DC    16
#define NBB   8            // b per CTA
#define ROWSC 128          // NBB * DC tasks per CTA
#define K0R   780          // unique symmetric pairs (i<=j)
#define K0P   800          // padded to multiple of 32
#define K1C   2496         // 39*64, already multiple of 32
#define KTOT  (K0P + K1C)  // 3296 folded weight rows
#define KCH   32           // K-chunk (4 k-steps of 8)
#define USTR  41           // sU row stride (floats)
#define HSTR  68           // sH row stride (floats)
#define WSTR  136          // sW row stride (floats), conflict-free B-frag loads

// SMEM layout (in floats)
#define OFF_U    0                   // 128*41  = 5248
#define OFF_H    5248                // 128*68  = 8704
#define OFF_W    13952               // 2*32*136= 8704
#define OFF_PAIR 22656               // 800 (uint32)
#define OFF_S    23456               // 128
#define OFF_WV   23584               // 192
#define SMEM_WORDS 23776
#define SMEM_BYTES (SMEM_WORDS * 4)  // 95104

// Folded + tf32-rounded weights, built by prologue each launch (deterministic).
__device__ __align__(16) float g_W[KTOT * 128];

__device__ __forceinline__ uint32_t f2tf32(float v) {
    uint32_t o;
    asm("cvt.rna.tf32.f32 %0, %1;" : "=r"(o) : "f"(v));
    return o;
}

// ---------------------------------------------------------------------------
// Prologue: fold f0 symmetric pairs, append f1, round everything to tf32.
// g_W rows 0..799  : layer-0 (row k<780 => W0[i,j]+W0[j,i] (i<j) or W0[i,i])
// g_W rows 800..   : layer-1 rows of f1
// ---------------------------------------------------------------------------
__global__ void fold_weights_kernel(const float* __restrict__ f0,
                                    const float* __restrict__ f1) {
    int idx = blockIdx.x * blockDim.x + threadIdx.x;
    if (idx >= KTOT * 128) return;
    int k = idx >> 7;
    int n = idx & 127;
    float v;
    if (k < K0P) {
        if (k < K0R) {
            int i = 0, base = 0;
            while (base + (F0C - i) <= k) { base += F0C - i; ++i; }
            int j = i + (k - base);
            v = f0[(i * F0C + j) * 128 + n];
            if (j != i) v += f0[(j * F0C + i) * 128 + n];
        } else {
            v = 0.0f;
        }
    } else {
        v = f1[(k - K0P) * 128 + n];
    }
    g_W[idx] = __uint_as_float(f2tf32(v));
}

// ---------------------------------------------------------------------------
// mma.sync m16n8k8 tf32: D = A(16x8,row) * B(8x8,col) + C
// ---------------------------------------------------------------------------
__device__ __forceinline__ void mma_tf32(float* c, const uint32_t* a,
                                         uint32_t b0, uint32_t b1) {
    asm volatile(
        "mma.sync.aligned.m16n8k8.row.col.f32.tf32.tf32.f32 "
        "{%0,%1,%2,%3}, {%4,%5,%6,%7}, {%8,%9}, {%0,%1,%2,%3};\n"
        : "+f"(c[0]), "+f"(c[1]), "+f"(c[2]), "+f"(c[3])
        : "r"(a[0]), "r"(a[1]), "r"(a[2]), "r"(a[3]), "r"(b0), "r"(b1));
}

__device__ __forceinline__ void cp_async16(float* dst, const float* src) {
    unsigned sa = (unsigned)__cvta_generic_to_shared(dst);
    asm volatile("cp.async.cg.shared.global [%0], [%1], 16;\n"
                 :: "r"(sa), "l"(src));
}

// Stage one 32x128 weight chunk (g_W rows grow0..grow0+31) into sW buffer.
__device__ __forceinline__ void stage_chunk(int grow0, float* dst, int tid) {
#pragma unroll
    for (int it = 0; it < 4; ++it) {
        int s = tid + it * 256;          // 1024 segments of 16B
        int row = s >> 5;
        int seg = s & 31;
        cp_async16(dst + row * WSTR + seg * 4,
                   g_W + (grow0 + row) * 128 + seg * 4);
    }
}

// ---------------------------------------------------------------------------
// Compute 4 k-steps (one 32-wide chunk) of the tiled GEMM.
// Warp tile: 32 rows (2 row-tiles) x 64 cols (8 n-tiles).
// PHASE 0: A[r,c] = u_i * u_j  (pair table),  PHASE 1: A[r,c] = u_{c>>6} * h_{c&63}
// ---------------------------------------------------------------------------
template <int PHASE>
__device__ __forceinline__ void compute_chunk(
    const float* __restrict__ sWbuf, const float* __restrict__ sU,
    const float* __restrict__ sH, const uint32_t* __restrict__ sPair,
    int kbase, int warp_m, int warp_n, int g, int tig,
    float acc[2][8][4]) {
#pragma unroll
    for (int ks = 0; ks < 4; ++ks) {
        int kloc = ks * 8;
        int kA = kbase + kloc;
        int c0 = kA + tig;
        int c1 = c0 + 4;

        int ia0, ja0, ia1, ja1;
        if (PHASE == 0) {
            uint32_t p0 = sPair[c0];
            uint32_t p1 = sPair[c1];
            ia0 = (int)(p0 >> 8); ja0 = (int)(p0 & 255u);
            ia1 = (int)(p1 >> 8); ja1 = (int)(p1 & 255u);
        } else {
            ia0 = c0 >> 6; ja0 = c0 & 63;
            ia1 = c1 >> 6; ja1 = c1 & 63;
        }

        uint32_t a[2][4];
#pragma unroll
        for (int rt = 0; rt < 2; ++rt) {
            int r0 = warp_m * 32 + rt * 16 + g;
            int r1 = r0 + 8;
            const float* u0 = sU + r0 * USTR;
            const float* u1 = sU + r1 * USTR;
            if (PHASE == 0) {
                a[rt][0] = f2tf32(u0[ia0] * u0[ja0]);
                a[rt][1] = f2tf32(u1[ia0] * u1[ja0]);
                a[rt][2] = f2tf32(u0[ia1] * u0[ja1]);
                a[rt][3] = f2tf32(u1[ia1] * u1[ja1]);
            } else {
                const float* h0 = sH + r0 * HSTR;
                const float* h1 = sH + r1 * HSTR;
                a[rt][0] = f2tf32(u0[ia0] * h0[ja0]);
                a[rt][1] = f2tf32(u1[ia0] * h1[ja0]);
                a[rt][2] = f2tf32(u0[ia1] * h0[ja1]);
                a[rt][3] = f2tf32(u1[ia1] * h1[ja1]);
            }
        }

#pragma unroll
        for (int nt = 0; nt < 8; ++nt) {
            int n = warp_n * 64 + nt * 8 + g;
            uint32_t b0 = __float_as_uint(sWbuf[(kloc + tig) * WSTR + n]);
            uint32_t b1 = __float_as_uint(sWbuf[(kloc + tig + 4) * WSTR + n]);
            mma_tf32(acc[0][nt], a[0], b0, b1);
            mma_tf32(acc[1][nt], a[1], b0, b1);
        }
    }
}

// Double-buffered pipeline over nchunks chunks starting at g_W row grow0.
template <int PHASE>
__device__ __forceinline__ void run_phase(
    int grow0, int nchunks, float* sW, const float* sU, const float* sH,
    const uint32_t* sPair, int tid, int warp_m, int warp_n, int g, int tig,
    float acc[2][8][4]) {
    stage_chunk(grow0, sW, tid);
    asm volatile("cp.async.commit_group;\n" ::);
    for (int c = 0; c < nchunks; ++c) {
        int cur = c & 1;
        if (c + 1 < nchunks) {
            stage_chunk(grow0 + (c + 1) * KCH, sW + (cur ^ 1) * (KCH * WSTR), tid);
            asm volatile("cp.async.commit_group;\n" ::);
            asm volatile("cp.async.wait_group 1;\n" ::);
        } else {
            asm volatile("cp.async.wait_group 0;\n" ::);
        }
        __syncthreads();
        compute_chunk<PHASE>(sW + cur * (KCH * WSTR), sU, sH, sPair,
                             c * KCH, warp_m, warp_n, g, tig, acc);
        __syncthreads();   // buffer reused two iterations later via next stage
    }
}

// ---------------------------------------------------------------------------
// Main kernel: 512 CTAs x 256 threads. CTA = 8 b x 16 d = 128 GEMM rows.
// ---------------------------------------------------------------------------
__global__ void __launch_bounds__(256, 2)
cin_kernel(const float* __restrict__ x, const float* __restrict__ wv,
           const float* __restrict__ bias, float* __restrict__ out) {
    extern __shared__ float smem[];
    float*    sU    = smem + OFF_U;
    float*    sH    = smem + OFF_H;
    float*    sW    = smem + OFF_W;
    uint32_t* sPair = (uint32_t*)(smem + OFF_PAIR);
    float*    sS    = smem + OFF_S;
    float*    sWv   = smem + OFF_WV;

    int tid  = threadIdx.x;
    int lane = tid & 31;
    int warp = tid >> 5;
    int g    = lane >> 2;     // groupID
    int tig  = lane & 3;      // threadID_in_group
    int warp_m = warp >> 1;   // 0..3 : row-tile group (32 rows)
    int warp_n = warp & 1;    // 0..1 : col half (64 cols)
    int b0 = blockIdx.x * NBB;

    if (tid < 128) sS[tid] = 0.0f;
    if (tid < 192) sWv[tid] = wv[tid];

    // Load x tile -> sU, tf32-rounded. Row r = bl*16 + d holds u = x[b0+bl,:,d].
    for (int idx = tid; idx < NBB * F0C * DC; idx += 256) {
        int bl  = idx / (F0C * DC);
        int rem = idx - bl * (F0C * DC);
        int i = rem >> 4;
        int d = rem & 15;
        float v = x[(b0 + bl) * (F0C * DC) + rem];
        sU[(bl * DC + d) * USTR + i] = __uint_as_float(f2tf32(v));
    }

    // Build symmetric pair table (k -> (i,j), i<=j). Padding rows map to (0,0)
    // whose weight rows are zero.
    for (int k = tid; k < K0P; k += 256) {
        uint32_t pk = 0;
        if (k < K0R) {
            int i = 0, base = 0;
            while (base + (F0C - i) <= k) { base += F0C - i; ++i; }
            int j = i + (k - base);
            pk = ((uint32_t)i << 8) | (uint32_t)j;
        }
        sPair[k] = pk;
    }
    __syncthreads();

    float acc[2][8][4];
#pragma unroll
    for (int rt = 0; rt < 2; ++rt)
#pragma unroll
        for (int nt = 0; nt < 8; ++nt)
#pragma unroll
            for (int q = 0; q < 4; ++q) acc[rt][nt][q] = 0.0f;

    // ---------------- Phase 0: z0 = relu(P0 @ W0folded) -------------------
    run_phase<0>(0, K0P / KCH, sW, sU, sH, sPair, tid, warp_m, warp_n, g, tig, acc);

    // Epilogue 0: cols 0..63 -> h (SMEM); cols 64..127 -> dot with w[0:64].
#pragma unroll
    for (int rt = 0; rt < 2; ++rt) {
        int r0 = warp_m * 32 + rt * 16 + g;
        int r1 = r0 + 8;
        if (warp_n == 0) {
#pragma unroll
            for (int nt = 0; nt < 8; ++nt) {
                int n = nt * 8 + 2 * tig;
                sH[r0 * HSTR + n]     = fmaxf(acc[rt][nt][0], 0.0f);
                sH[r0 * HSTR + n + 1] = fmaxf(acc[rt][nt][1], 0.0f);
                sH[r1 * HSTR + n]     = fmaxf(acc[rt][nt][2], 0.0f);
                sH[r1 * HSTR + n + 1] = fmaxf(acc[rt][nt][3], 0.0f);
            }
        } else {
            float s0 = 0.0f, s1 = 0.0f;
#pragma unroll
            for (int nt = 0; nt < 8; ++nt) {
                int f = nt * 8 + 2 * tig;      // w index = global col - 64
                float w0 = sWv[f], w1 = sWv[f + 1];
                s0 += fmaxf(acc[rt][nt][0], 0.0f) * w0 + fmaxf(acc[rt][nt][1], 0.0f) * w1;
                s1 += fmaxf(acc[rt][nt][2], 0.0f) * w0 + fmaxf(acc[rt][nt][3], 0.0f) * w1;
            }
            s0 += __shfl_xor_sync(0xffffffffu, s0, 1);
            s0 += __shfl_xor_sync(0xffffffffu, s0, 2);
            s1 += __shfl_xor_sync(0xffffffffu, s1, 1);
            s1 += __shfl_xor_sync(0xffffffffu, s1, 2);
            if (tig == 0) {
                atomicAdd(&sS[r0], s0);
                atomicAdd(&sS[r1], s1);
            }
        }
    }
    __syncthreads();   // sH complete before phase 1 reads it (also: acc reuse)

#pragma unroll
    for (int rt = 0; rt < 2; ++rt)
#pragma unroll
        for (int nt = 0; nt < 8; ++nt)
#pragma unroll
            for (int q = 0; q < 4; ++q) acc[rt][nt][q] = 0.0f;

    // ---------------- Phase 1: z1 = relu(P1 @ W1) --------------------------
    run_phase<1>(K0P, K1C / KCH, sW, sU, sH, sPair, tid, warp_m, warp_n, g, tig, acc);

    // Epilogue 1: all 128 cols dotted with w[64:192].
#pragma unroll
    for (int rt = 0; rt < 2; ++rt) {
        int r0 = warp_m * 32 + rt * 16 + g;
        int r1 = r0 + 8;
        float s0 = 0.0f, s1 = 0.0f;
#pragma unroll
        for (int nt = 0; nt < 8; ++nt) {
            int f = 64 + warp_n * 64 + nt * 8 + 2 * tig;
            float w0 = sWv[f], w1 = sWv[f + 1];
            s0 += fmaxf(acc[rt][nt][0], 0.0f) * w0 + fmaxf(acc[rt][nt][1], 0.0f) * w1;
            s1 += fmaxf(acc[rt][nt][2], 0.0f) * w0 + fmaxf(acc[rt][nt][3], 0.0f) * w1;
        }
        s0 += __shfl_xor_sync(0xffffffffu, s0, 1);
        s0 += __shfl_xor_sync(0xffffffffu, s0, 2);
        s1 += __shfl_xor_sync(0xffffffffu, s1, 1);
        s1 += __shfl_xor_sync(0xffffffffu, s1, 2);
        if (tig == 0) {
            atomicAdd(&sS[r0], s0);
            atomicAdd(&sS[r1], s1);
        }
    }
    __syncthreads();

    // Final: out[b] = bias + sum_d sS[bl*16 + d]
    if (tid < NBB) {
        float s = bias[0];
#pragma unroll
        for (int d = 0; d < DC; ++d) s += sS[tid * DC + d];
        out[b0 + tid] = s;
    }
}

// ---------------------------------------------------------------------------
extern "C" void kernel_launch(void* const* d_in, const int* in_sizes, int n_in,
                              void* d_out, int out_size) {
    (void)in_sizes; (void)n_in; (void)out_size;
    const float* x  = (const float*)d_in[0];
    const float* f0 = (const float*)d_in[1];
    const float* f1 = (const float*)d_in[2];
    const float* wv = (const float*)d_in[3];
    const float* bb = (const float*)d_in[4];
    float* out = (float*)d_out;

    // Opt in to >48KB dynamic SMEM (attribute set is not a stream op; safe
    // to call every launch, including during graph capture).
    cudaFuncSetAttribute(cin_kernel,
                         cudaFuncAttributeMaxDynamicSharedMemorySize,
                         SMEM_BYTES);

    fold_weights_kernel<<<(KTOT * 128 + 255) / 256, 256>>>(f0, f1);
    cin_kernel<<<512, 256, SMEM_BYTES>>>(x, wv, bb, out);
}

// round 11
// speedup vs baseline: 1.6473x; 1.6473x over previous
#include <cuda_runtime.h>
#include <cuda_fp16.h>
#include <stdint.h>

// ---------------------------------------------------------------------------
// Problem constants
// ---------------------------------------------------------------------------
#define F0C   39
#define DC    16
#define NBB   8                  // batches per CTA (8 b x 16 d = 128 GEMM rows)
#define K0R   780                // unique symmetric pairs (i<=j)
#define K0P   800                // padded to multiple of 32
#define K1C   2496               // 39*64
#define KTOT  (K0P + K1C)        // 3296
#define KCH   32                 // k per chunk (2 mma k-steps of 16)
#define NCHT  (KTOT / KCH)       // 103
#define CH0   (K0P / KCH)        // 25
#define USTR  41                 // sU row stride (floats), conflict-free
#define HSTR  68                 // sH row stride (floats), float2-aligned

// W tile in SMEM: 32 k-rows x 128 n (fp16), row padded to 136 halves = 272 B
// -> ldmatrix rows hit banks 4(r+nt)..+3: conflict-free.
#define WROWB 272
#define WBUFB (32 * WROWB)       // 8704 bytes per buffer
#define WBUFW (WBUFB / 4)        // 2176 words

// SMEM layout (float-word offsets)
#define OFF_W    0               // 4 buffers x 2176 = 8704
#define OFF_U    8704            // 128 x 41 = 5248
#define OFF_H    13952           // 128 x 68 = 8704
#define OFF_PAIR 22656           // 800
#define OFF_S    23456           // 128
#define OFF_WV   23584           // 192
#define SMEM_WORDS 23776
#define SMEM_BYTES (SMEM_WORDS * 4)   // 95104 -> 2 CTAs/SM

// Folded fp16 weights, k-major: g_W[k*128 + n].
__device__ __align__(16) __half g_W[KTOT * 128];

// ---------------------------------------------------------------------------
// Helpers
// ---------------------------------------------------------------------------
__device__ __forceinline__ uint32_t pack2(float lo, float hi) {
    __half2 h = __floats2half2_rn(lo, hi);   // lo -> low 16 bits (smaller k)
    return *(uint32_t*)&h;
}

__device__ __forceinline__ void cp_async16(void* dst, const void* src) {
    unsigned sa = (unsigned)__cvta_generic_to_shared(dst);
    asm volatile("cp.async.cg.shared.global [%0], [%1], 16;\n"
                 :: "r"(sa), "l"(src));
}

__device__ __forceinline__ void ldmx2t(uint32_t& b0, uint32_t& b1, uint32_t addr) {
    asm volatile("ldmatrix.sync.aligned.m8n8.x2.trans.shared.b16 {%0,%1}, [%2];"
                 : "=r"(b0), "=r"(b1) : "r"(addr));
}

// D(16x8,f32) += A(16x16,f16) * B(16x8,f16)
__device__ __forceinline__ void mma_fp16(float* c, const uint32_t* a,
                                         uint32_t b0, uint32_t b1) {
    asm volatile(
        "mma.sync.aligned.m16n8k16.row.col.f32.f16.f16.f32 "
        "{%0,%1,%2,%3}, {%4,%5,%6,%7}, {%8,%9}, {%0,%1,%2,%3};\n"
        : "+f"(c[0]), "+f"(c[1]), "+f"(c[2]), "+f"(c[3])
        : "r"(a[0]), "r"(a[1]), "r"(a[2]), "r"(a[3]), "r"(b0), "r"(b1));
}

// ---------------------------------------------------------------------------
// Prologue: fold f0 symmetric pairs + append f1, rounded to fp16, k-major.
// ---------------------------------------------------------------------------
__global__ void fold_weights_kernel(const float* __restrict__ f0,
                                    const float* __restrict__ f1) {
    int idx = blockIdx.x * blockDim.x + threadIdx.x;
    if (idx >= KTOT * 128) return;
    int k = idx >> 7;
    int n = idx & 127;
    float v;
    if (k < K0P) {
        if (k < K0R) {
            int i = 0, base = 0;
            while (base + (F0C - i) <= k) { base += F0C - i; ++i; }
            int j = i + (k - base);
            v = f0[(i * F0C + j) * 128 + n];
            if (j != i) v += f0[(j * F0C + i) * 128 + n];
        } else {
            v = 0.0f;
        }
    } else {
        v = f1[(k - K0P) * 128 + n];
    }
    g_W[idx] = __float2half_rn(v);
}

// Stage one 32x128 fp16 W chunk into a 272B-stride SMEM buffer.
__device__ __forceinline__ void stage_w(int chunk, char* dst, int tid) {
#pragma unroll
    for (int it = 0; it < 2; ++it) {
        int s = tid + it * 256;          // 512 segments of 16B
        int row = s >> 4;
        int seg = s & 15;
        cp_async16(dst + row * WROWB + seg * 16,
                   g_W + (size_t)(chunk * 32 + row) * 128 + seg * 8);
    }
}

// ---------------------------------------------------------------------------
// One 32-k chunk: build A fragments (on-the-fly products -> fp16 pairs),
// ldmatrix B fragments, 32 MMAs. Warp tile: 32 rows x 64 cols.
// ---------------------------------------------------------------------------
template <int PHASE>
__device__ __forceinline__ void compute_chunk(
    int c, uint32_t wbuf, const float* __restrict__ sU,
    const float* __restrict__ sH, const uint32_t* __restrict__ sPair,
    int warp_m, int warp_n, int g, int tig, int lane, float acc[2][8][4]) {

    uint32_t a[2][2][4];   // [rowtile][kstep][areg]

    const int R0 = warp_m * 32 + g;
    if (PHASE == 0) {
        const int kb = c * KCH;
        const float* u0  = sU + R0 * USTR;
        const float* u8  = u0 + 8 * USTR;
        const float* u16 = u0 + 16 * USTR;
        const float* u24 = u0 + 24 * USTR;
#pragma unroll
        for (int ks = 0; ks < 2; ++ks) {
#pragma unroll
            for (int h2 = 0; h2 < 2; ++h2) {
                int kA = kb + ks * 16 + h2 * 8 + tig * 2;
                uint32_t p0 = sPair[kA], p1 = sPair[kA + 1];
                int i0 = p0 >> 8, j0 = p0 & 255u;
                int i1 = p1 >> 8, j1 = p1 & 255u;
                a[0][ks][h2 * 2 + 0] = pack2(u0[i0] * u0[j0],  u0[i1] * u0[j1]);
                a[0][ks][h2 * 2 + 1] = pack2(u8[i0] * u8[j0],  u8[i1] * u8[j1]);
                a[1][ks][h2 * 2 + 0] = pack2(u16[i0] * u16[j0], u16[i1] * u16[j1]);
                a[1][ks][h2 * 2 + 1] = pack2(u24[i0] * u24[j0], u24[i1] * u24[j1]);
            }
        }
    } else {
        const int kb1 = (c - CH0) * KCH;
        const int iu = kb1 >> 6;
        const int jb = kb1 & 63;
        float ui0  = sU[(R0     ) * USTR + iu];
        float ui8  = sU[(R0 +  8) * USTR + iu];
        float ui16 = sU[(R0 + 16) * USTR + iu];
        float ui24 = sU[(R0 + 24) * USTR + iu];
        const float* h0  = sH + (R0     ) * HSTR + jb;
        const float* h8  = sH + (R0 +  8) * HSTR + jb;
        const float* h16 = sH + (R0 + 16) * HSTR + jb;
        const float* h24 = sH + (R0 + 24) * HSTR + jb;
#pragma unroll
        for (int ks = 0; ks < 2; ++ks) {
#pragma unroll
            for (int h2 = 0; h2 < 2; ++h2) {
                int jA = ks * 16 + h2 * 8 + tig * 2;
                float2 v0  = *(const float2*)(h0 + jA);
                float2 v8  = *(const float2*)(h8 + jA);
                float2 v16 = *(const float2*)(h16 + jA);
                float2 v24 = *(const float2*)(h24 + jA);
                a[0][ks][h2 * 2 + 0] = pack2(ui0 * v0.x,   ui0 * v0.y);
                a[0][ks][h2 * 2 + 1] = pack2(ui8 * v8.x,   ui8 * v8.y);
                a[1][ks][h2 * 2 + 0] = pack2(ui16 * v16.x, ui16 * v16.y);
                a[1][ks][h2 * 2 + 1] = pack2(ui24 * v24.x, ui24 * v24.y);
            }
        }
    }

    // B fragments + MMAs. ldmatrix row address: lane L (0..15) -> k-row L.
    uint32_t wbase = wbuf + (uint32_t)(lane & 15) * WROWB + warp_n * 128;
#pragma unroll
    for (int ks = 0; ks < 2; ++ks) {
#pragma unroll
        for (int nt = 0; nt < 8; ++nt) {
            uint32_t b0, b1;
            ldmx2t(b0, b1, wbase + ks * (16 * WROWB) + nt * 16);
            mma_fp16(acc[0][nt], a[0][ks], b0, b1);
            mma_fp16(acc[1][nt], a[1][ks], b0, b1);
        }
    }
}

// ---------------------------------------------------------------------------
// Main kernel: 512 CTAs x 256 threads. CTA = 8 b x 16 d = 128 GEMM rows.
// ---------------------------------------------------------------------------
__global__ void __launch_bounds__(256, 2)
cin_kernel(const float* __restrict__ x, const float* __restrict__ wv,
           const float* __restrict__ bias, float* __restrict__ out) {
    extern __shared__ __align__(16) float smem[];
    char*     sW    = (char*)(smem + OFF_W);
    float*    sU    = smem + OFF_U;
    float*    sH    = smem + OFF_H;
    uint32_t* sPair = (uint32_t*)(smem + OFF_PAIR);
    float*    sS    = smem + OFF_S;
    float*    sWv   = smem + OFF_WV;

    int tid  = threadIdx.x;
    int lane = tid & 31;
    int warp = tid >> 5;
    int g    = lane >> 2;
    int tig  = lane & 3;
    int warp_m = warp >> 1;
    int warp_n = warp & 1;
    int b0 = blockIdx.x * NBB;

    uint32_t wbase_u32 = (uint32_t)__cvta_generic_to_shared(sW);

    // Prefetch W chunks 0 and 1 immediately.
    stage_w(0, sW, tid);
    asm volatile("cp.async.commit_group;\n" ::);
    stage_w(1, sW + WBUFB, tid);
    asm volatile("cp.async.commit_group;\n" ::);

    if (tid < 128) sS[tid] = 0.0f;
    if (tid < 192) sWv[tid] = wv[tid];

    // Load x tile -> sU (full fp32; product rounds to fp16 once later).
    for (int idx = tid; idx < NBB * F0C * DC; idx += 256) {
        int bl  = idx / (F0C * DC);
        int rem = idx - bl * (F0C * DC);
        int i = rem >> 4;
        int d = rem & 15;
        sU[(bl * DC + d) * USTR + i] = x[(b0 + bl) * (F0C * DC) + rem];
    }

    // Symmetric pair table; padding k -> (0,0) with zero W rows.
    for (int k = tid; k < K0P; k += 256) {
        uint32_t pk = 0;
        if (k < K0R) {
            int i = 0, base = 0;
            while (base + (F0C - i) <= k) { base += F0C - i; ++i; }
            int j = i + (k - base);
            pk = ((uint32_t)i << 8) | (uint32_t)j;
        }
        sPair[k] = pk;
    }
    __syncthreads();

    float acc[2][8][4];
#pragma unroll
    for (int rt = 0; rt < 2; ++rt)
#pragma unroll
        for (int nt = 0; nt < 8; ++nt)
#pragma unroll
            for (int q = 0; q < 4; ++q) acc[rt][nt][q] = 0.0f;

    for (int c = 0; c < NCHT; ++c) {
        // Stage W[c+2] into buffer (c+2)&3 (read two iterations from now;
        // its previous contents were consumed in iteration c-2).
        if (c + 2 < NCHT)
            stage_w(c + 2, sW + ((c + 2) & 3) * WBUFB, tid);
        asm volatile("cp.async.commit_group;\n" ::);
        asm volatile("cp.async.wait_group 2;\n" ::);   // W[c] resident
        __syncthreads();

        if (c == CH0) {
            // ---- Epilogue 0: cols 0..63 -> h; cols 64..127 -> dot w[0:64].
#pragma unroll
            for (int rt = 0; rt < 2; ++rt) {
                int r0 = warp_m * 32 + rt * 16 + g;
                int r1 = r0 + 8;
                if (warp_n == 0) {
#pragma unroll
                    for (int nt = 0; nt < 8; ++nt) {
                        int n = nt * 8 + 2 * tig;
                        sH[r0 * HSTR + n]     = fmaxf(acc[rt][nt][0], 0.0f);
                        sH[r0 * HSTR + n + 1] = fmaxf(acc[rt][nt][1], 0.0f);
                        sH[r1 * HSTR + n]     = fmaxf(acc[rt][nt][2], 0.0f);
                        sH[r1 * HSTR + n + 1] = fmaxf(acc[rt][nt][3], 0.0f);
                    }
                } else {
                    float s0 = 0.0f, s1 = 0.0f;
#pragma unroll
                    for (int nt = 0; nt < 8; ++nt) {
                        int f = nt * 8 + 2 * tig;
                        float w0 = sWv[f], w1 = sWv[f + 1];
                        s0 += fmaxf(acc[rt][nt][0], 0.0f) * w0 +
                              fmaxf(acc[rt][nt][1], 0.0f) * w1;
                        s1 += fmaxf(acc[rt][nt][2], 0.0f) * w0 +
                              fmaxf(acc[rt][nt][3], 0.0f) * w1;
                    }
                    s0 += __shfl_xor_sync(0xffffffffu, s0, 1);
                    s0 += __shfl_xor_sync(0xffffffffu, s0, 2);
                    s1 += __shfl_xor_sync(0xffffffffu, s1, 1);
                    s1 += __shfl_xor_sync(0xffffffffu, s1, 2);
                    if (tig == 0) {
                        atomicAdd(&sS[r0], s0);
                        atomicAdd(&sS[r1], s1);
                    }
                }
            }
#pragma unroll
            for (int rt = 0; rt < 2; ++rt)
#pragma unroll
                for (int nt = 0; nt < 8; ++nt)
#pragma unroll
                    for (int q = 0; q < 4; ++q) acc[rt][nt][q] = 0.0f;
            __syncthreads();   // sH visible to all warps before phase-1 builds
        }

        uint32_t wbuf = wbase_u32 + (c & 3) * WBUFB;
        if (c < CH0)
            compute_chunk<0>(c, wbuf, sU, sH, sPair, warp_m, warp_n, g, tig,
                             lane, acc);
        else
            compute_chunk<1>(c, wbuf, sU, sH, sPair, warp_m, warp_n, g, tig,
                             lane, acc);
    }

    // ---- Epilogue 1: all 128 cols dotted with w[64:192].
#pragma unroll
    for (int rt = 0; rt < 2; ++rt) {
        int r0 = warp_m * 32 + rt * 16 + g;
        int r1 = r0 + 8;
        float s0 = 0.0f, s1 = 0.0f;
#pragma unroll
        for (int nt = 0; nt < 8; ++nt) {
            int f = 64 + warp_n * 64 + nt * 8 + 2 * tig;
            float w0 = sWv[f], w1 = sWv[f + 1];
            s0 += fmaxf(acc[rt][nt][0], 0.0f) * w0 +
                  fmaxf(acc[rt][nt][1], 0.0f) * w1;
            s1 += fmaxf(acc[rt][nt][2], 0.0f) * w0 +
                  fmaxf(acc[rt][nt][3], 0.0f) * w1;
        }
        s0 += __shfl_xor_sync(0xffffffffu, s0, 1);
        s0 += __shfl_xor_sync(0xffffffffu, s0, 2);
        s1 += __shfl_xor_sync(0xffffffffu, s1, 1);
        s1 += __shfl_xor_sync(0xffffffffu, s1, 2);
        if (tig == 0) {
            atomicAdd(&sS[r0], s0);
            atomicAdd(&sS[r1], s1);
        }
    }
    __syncthreads();

    // out[b] = bias + sum_d sS[bl*16 + d]
    if (tid < NBB) {
        float s = bias[0];
#pragma unroll
        for (int d = 0; d < DC; ++d) s += sS[tid * DC + d];
        out[b0 + tid] = s;
    }
}

// ---------------------------------------------------------------------------
extern "C" void kernel_launch(void* const* d_in, const int* in_sizes, int n_in,
                              void* d_out, int out_size) {
    (void)in_sizes; (void)n_in; (void)out_size;
    const float* x  = (const float*)d_in[0];
    const float* f0 = (const float*)d_in[1];
    const float* f1 = (const float*)d_in[2];
    const float* wv = (const float*)d_in[3];
    const float* bb = (const float*)d_in[4];
    float* out = (float*)d_out;

    cudaFuncSetAttribute(cin_kernel,
                         cudaFuncAttributeMaxDynamicSharedMemorySize,
                         SMEM_BYTES);

    fold_weights_kernel<<<(KTOT * 128 + 255) / 256, 256>>>(f0, f1);
    cin_kernel<<<512, 256, SMEM_BYTES>>>(x, wv, bb, out);
}

// round 13
// speedup vs baseline: 2.0159x; 1.2238x over previous
#include <cuda_runtime.h>
#include <cuda_fp16.h>
#include <stdint.h>

// ---------------------------------------------------------------------------
// Problem constants
// ---------------------------------------------------------------------------
#define F0C   39
#define DC    16
#define NBB   8                  // batches per CTA (8 b x 16 d = 128 GEMM rows)
#define K0R   780                // unique symmetric pairs (i<=j)
#define K0P   800                // padded to multiple of 32
#define K1C   2496               // 39*64
#define KTOT  (K0P + K1C)        // 3296
#define KCH   32                 // k per chunk (2 mma k-steps of 16)
#define NCHT  (KTOT / KCH)       // 103
#define CH0   (K0P / KCH)        // 25
#define USTR  41                 // sU row stride (floats), conflict-free
#define HSTRH 72                 // sH row stride in HALVES (144 B): bank 4g+tig

// W tile in SMEM: 32 k-rows x 128 n (fp16), row padded to 136 halves = 272 B
#define WROWB 272
#define WBUFB (32 * WROWB)       // 8704 bytes per buffer

// SMEM layout (float-word offsets)
#define OFF_W    0               // 4 buffers x 2176 words = 8704
#define OFF_U    8704            // 128 x 41 = 5248
#define OFF_H    13952           // 128 x 72 halves = 4608 words
#define OFF_PAIR 18560           // 400 words (800 packed ushort pairs)
#define OFF_S    18960           // 128
#define OFF_WV   19088           // 192
#define SMEM_WORDS 19280
#define SMEM_BYTES (SMEM_WORDS * 4)   // 77120 -> 2 CTAs/SM (reg-limited anyway)

// Folded fp16 weights, k-major: g_W[k*128 + n].
__device__ __align__(16) __half g_W[KTOT * 128];

// ---------------------------------------------------------------------------
// Helpers
// ---------------------------------------------------------------------------
__device__ __forceinline__ uint32_t pack2(float lo, float hi) {
    __half2 h = __floats2half2_rn(lo, hi);   // lo -> low 16 bits (smaller k)
    return *(uint32_t*)&h;
}

__device__ __forceinline__ uint32_t hmul2_u32(__half2 u, uint32_t hv) {
    __half2 r = __hmul2(u, *(__half2*)&hv);
    return *(uint32_t*)&r;
}

__device__ __forceinline__ void cp_async16(void* dst, const void* src) {
    unsigned sa = (unsigned)__cvta_generic_to_shared(dst);
    asm volatile("cp.async.cg.shared.global [%0], [%1], 16;\n"
                 :: "r"(sa), "l"(src));
}

// x4 trans: lanes 0-15 give rows of matrices 0/1 (k 0-7 / 8-15, n-tile nt),
// lanes 16-31 give rows of matrices 2/3 (same k-rows, n-tile nt+1, +16 B).
__device__ __forceinline__ void ldmx4t(uint32_t& b0, uint32_t& b1,
                                       uint32_t& b2, uint32_t& b3,
                                       uint32_t addr) {
    asm volatile(
        "ldmatrix.sync.aligned.m8n8.x4.trans.shared.b16 {%0,%1,%2,%3}, [%4];"
        : "=r"(b0), "=r"(b1), "=r"(b2), "=r"(b3) : "r"(addr));
}

// D(16x8,f32) += A(16x16,f16) * B(16x8,f16)
__device__ __forceinline__ void mma_fp16(float* c, const uint32_t* a,
                                         uint32_t b0, uint32_t b1) {
    asm volatile(
        "mma.sync.aligned.m16n8k16.row.col.f32.f16.f16.f32 "
        "{%0,%1,%2,%3}, {%4,%5,%6,%7}, {%8,%9}, {%0,%1,%2,%3};\n"
        : "+f"(c[0]), "+f"(c[1]), "+f"(c[2]), "+f"(c[3])
        : "r"(a[0]), "r"(a[1]), "r"(a[2]), "r"(a[3]), "r"(b0), "r"(b1));
}

// ---------------------------------------------------------------------------
// Prologue: fold f0 symmetric pairs + append f1, rounded to fp16, k-major.
// ---------------------------------------------------------------------------
__global__ void fold_weights_kernel(const float* __restrict__ f0,
                                    const float* __restrict__ f1) {
    int idx = blockIdx.x * blockDim.x + threadIdx.x;
    if (idx >= KTOT * 128) return;
    int k = idx >> 7;
    int n = idx & 127;
    float v;
    if (k < K0P) {
        if (k < K0R) {
            int i = 0, base = 0;
            while (base + (F0C - i) <= k) { base += F0C - i; ++i; }
            int j = i + (k - base);
            v = f0[(i * F0C + j) * 128 + n];
            if (j != i) v += f0[(j * F0C + i) * 128 + n];
        } else {
            v = 0.0f;
        }
    } else {
        v = f1[(k - K0P) * 128 + n];
    }
    g_W[idx] = __float2half_rn(v);
}

// Stage one 32x128 fp16 W chunk into a 272B-stride SMEM buffer.
__device__ __forceinline__ void stage_w(int chunk, char* dst, int tid) {
#pragma unroll
    for (int it = 0; it < 2; ++it) {
        int s = tid + it * 256;          // 512 segments of 16B
        int row = s >> 4;
        int seg = s & 15;
        cp_async16(dst + row * WROWB + seg * 16,
                   g_W + (size_t)(chunk * 32 + row) * 128 + seg * 8);
    }
}

// ---------------------------------------------------------------------------
// One 32-k chunk. Warp tile: 32 rows x 64 cols.
// ---------------------------------------------------------------------------
template <int PHASE>
__device__ __forceinline__ void compute_chunk(
    int c, uint32_t wbuf, const float* __restrict__ sU,
    const __half* __restrict__ sH, const uint32_t* __restrict__ sPairP,
    int warp_m, int warp_n, int g, int tig, int lane, float acc[2][8][4]) {

    uint32_t a[2][2][4];   // [rowtile][kstep][areg]
    const int R0 = warp_m * 32 + g;

    if (PHASE == 0) {
        const int kb = c * KCH;
        const float* u0  = sU + R0 * USTR;
        const float* u8  = u0 + 8 * USTR;
        const float* u16 = u0 + 16 * USTR;
        const float* u24 = u0 + 24 * USTR;
#pragma unroll
        for (int ks = 0; ks < 2; ++ks) {
#pragma unroll
            for (int h2 = 0; h2 < 2; ++h2) {
                int kA = kb + ks * 16 + h2 * 8 + tig * 2;
                uint32_t pp = sPairP[kA >> 1];       // two packed (i<<8)|j
                int j0 = pp & 255u,          i0 = (pp >> 8) & 255u;
                int j1 = (pp >> 16) & 255u,  i1 = pp >> 24;
                a[0][ks][h2 * 2 + 0] = pack2(u0[i0] * u0[j0],  u0[i1] * u0[j1]);
                a[0][ks][h2 * 2 + 1] = pack2(u8[i0] * u8[j0],  u8[i1] * u8[j1]);
                a[1][ks][h2 * 2 + 0] = pack2(u16[i0] * u16[j0], u16[i1] * u16[j1]);
                a[1][ks][h2 * 2 + 1] = pack2(u24[i0] * u24[j0], u24[i1] * u24[j1]);
            }
        }
    } else {
        const int kb1 = (c - CH0) * KCH;
        const int iu = kb1 >> 6;
        const int jb = kb1 & 63;
        __half2 uh0  = __float2half2_rn(sU[(R0     ) * USTR + iu]);
        __half2 uh8  = __float2half2_rn(sU[(R0 +  8) * USTR + iu]);
        __half2 uh16 = __float2half2_rn(sU[(R0 + 16) * USTR + iu]);
        __half2 uh24 = __float2half2_rn(sU[(R0 + 24) * USTR + iu]);
        const __half* h0  = sH + (R0     ) * HSTRH + jb;
        const __half* h8  = sH + (R0 +  8) * HSTRH + jb;
        const __half* h16 = sH + (R0 + 16) * HSTRH + jb;
        const __half* h24 = sH + (R0 + 24) * HSTRH + jb;
#pragma unroll
        for (int ks = 0; ks < 2; ++ks) {
#pragma unroll
            for (int h2 = 0; h2 < 2; ++h2) {
                int jA = ks * 16 + h2 * 8 + tig * 2;
                a[0][ks][h2 * 2 + 0] = hmul2_u32(uh0,  *(const uint32_t*)(h0  + jA));
                a[0][ks][h2 * 2 + 1] = hmul2_u32(uh8,  *(const uint32_t*)(h8  + jA));
                a[1][ks][h2 * 2 + 0] = hmul2_u32(uh16, *(const uint32_t*)(h16 + jA));
                a[1][ks][h2 * 2 + 1] = hmul2_u32(uh24, *(const uint32_t*)(h24 + jA));
            }
        }
    }

    // B fragments (x4.trans, 2 n-tiles per op) + 32 MMAs.
    uint32_t wbase = wbuf + (uint32_t)(lane & 15) * WROWB + warp_n * 128 +
                     ((lane >> 4) & 1) * 16;
#pragma unroll
    for (int ks = 0; ks < 2; ++ks) {
#pragma unroll
        for (int nt2 = 0; nt2 < 4; ++nt2) {
            uint32_t b0, b1, b2, b3;
            ldmx4t(b0, b1, b2, b3, wbase + ks * (16 * WROWB) + nt2 * 32);
            mma_fp16(acc[0][nt2 * 2],     a[0][ks], b0, b1);
            mma_fp16(acc[1][nt2 * 2],     a[1][ks], b0, b1);
            mma_fp16(acc[0][nt2 * 2 + 1], a[0][ks], b2, b3);
            mma_fp16(acc[1][nt2 * 2 + 1], a[1][ks], b2, b3);
        }
    }
}

// ---------------------------------------------------------------------------
// Main kernel: 512 CTAs x 256 threads. CTA = 8 b x 16 d = 128 GEMM rows.
// ---------------------------------------------------------------------------
__global__ void __launch_bounds__(256, 2)
cin_kernel(const float* __restrict__ x, const float* __restrict__ wv,
           const float* __restrict__ bias, float* __restrict__ out) {
    extern __shared__ __align__(16) float smem[];
    char*     sW     = (char*)(smem + OFF_W);
    float*    sU     = smem + OFF_U;
    __half*   sH     = (__half*)(smem + OFF_H);
    uint32_t* sPairP = (uint32_t*)(smem + OFF_PAIR);
    float*    sS     = smem + OFF_S;
    float*    sWv    = smem + OFF_WV;

    int tid  = threadIdx.x;
    int lane = tid & 31;
    int warp = tid >> 5;
    int g    = lane >> 2;
    int tig  = lane & 3;
    int warp_m = warp >> 1;
    int warp_n = warp & 1;
    int b0 = blockIdx.x * NBB;

    uint32_t wbase_u32 = (uint32_t)__cvta_generic_to_shared(sW);

    // Prefetch W chunks 0 and 1 immediately.
    stage_w(0, sW, tid);
    asm volatile("cp.async.commit_group;\n" ::);
    stage_w(1, sW + WBUFB, tid);
    asm volatile("cp.async.commit_group;\n" ::);

    if (tid < 128) sS[tid] = 0.0f;
    if (tid < 192) sWv[tid] = wv[tid];

    // Load x tile -> sU (fp32).
    for (int idx = tid; idx < NBB * F0C * DC; idx += 256) {
        int bl  = idx / (F0C * DC);
        int rem = idx - bl * (F0C * DC);
        int i = rem >> 4;
        int d = rem & 15;
        sU[(bl * DC + d) * USTR + i] = x[(b0 + bl) * (F0C * DC) + rem];
    }

    // Packed symmetric pair table: word e holds k=2e (lo16) and k=2e+1 (hi16),
    // each as (i<<8)|j. Padding k -> (0,0); matching W rows are zero.
    for (int e = tid; e < K0P / 2; e += 256) {
        uint32_t w = 0;
#pragma unroll
        for (int h = 0; h < 2; ++h) {
            int k = 2 * e + h;
            uint32_t pk = 0;
            if (k < K0R) {
                int i = 0, base = 0;
                while (base + (F0C - i) <= k) { base += F0C - i; ++i; }
                int j = i + (k - base);
                pk = ((uint32_t)i << 8) | (uint32_t)j;
            }
            w |= pk << (16 * h);
        }
        sPairP[e] = w;
    }
    __syncthreads();

    float acc[2][8][4];
#pragma unroll
    for (int rt = 0; rt < 2; ++rt)
#pragma unroll
        for (int nt = 0; nt < 8; ++nt)
#pragma unroll
            for (int q = 0; q < 4; ++q) acc[rt][nt][q] = 0.0f;

    for (int c = 0; c < NCHT; ++c) {
        // Stage W[c+2] into buffer (c+2)&3 (its old contents, chunk c-2, were
        // consumed before the syncthreads of iteration c-1).
        if (c + 2 < NCHT)
            stage_w(c + 2, sW + ((c + 2) & 3) * WBUFB, tid);
        asm volatile("cp.async.commit_group;\n" ::);
        asm volatile("cp.async.wait_group 2;\n" ::);   // W[c] resident
        __syncthreads();

        if (c == CH0) {
            // ---- Epilogue 0: cols 0..63 -> h (fp16); cols 64..127 -> dot.
#pragma unroll
            for (int rt = 0; rt < 2; ++rt) {
                int r0 = warp_m * 32 + rt * 16 + g;
                int r1 = r0 + 8;
                if (warp_n == 0) {
#pragma unroll
                    for (int nt = 0; nt < 8; ++nt) {
                        int n = nt * 8 + 2 * tig;
                        *(__half2*)(sH + r0 * HSTRH + n) = __floats2half2_rn(
                            fmaxf(acc[rt][nt][0], 0.0f),
                            fmaxf(acc[rt][nt][1], 0.0f));
                        *(__half2*)(sH + r1 * HSTRH + n) = __floats2half2_rn(
                            fmaxf(acc[rt][nt][2], 0.0f),
                            fmaxf(acc[rt][nt][3], 0.0f));
                    }
                } else {
                    float s0 = 0.0f, s1 = 0.0f;
#pragma unroll
                    for (int nt = 0; nt < 8; ++nt) {
                        int f = nt * 8 + 2 * tig;
                        float w0 = sWv[f], w1 = sWv[f + 1];
                        s0 += fmaxf(acc[rt][nt][0], 0.0f) * w0 +
                              fmaxf(acc[rt][nt][1], 0.0f) * w1;
                        s1 += fmaxf(acc[rt][nt][2], 0.0f) * w0 +
                              fmaxf(acc[rt][nt][3], 0.0f) * w1;
                    }
                    s0 += __shfl_xor_sync(0xffffffffu, s0, 1);
                    s0 += __shfl_xor_sync(0xffffffffu, s0, 2);
                    s1 += __shfl_xor_sync(0xffffffffu, s1, 1);
                    s1 += __shfl_xor_sync(0xffffffffu, s1, 2);
                    if (tig == 0) {
                        atomicAdd(&sS[r0], s0);
                        atomicAdd(&sS[r1], s1);
                    }
                }
            }
#pragma unroll
            for (int rt = 0; rt < 2; ++rt)
#pragma unroll
                for (int nt = 0; nt < 8; ++nt)
#pragma unroll
                    for (int q = 0; q < 4; ++q) acc[rt][nt][q] = 0.0f;
            __syncthreads();   // sH visible to all warps before phase-1 builds
        }

        uint32_t wbuf = wbase_u32 + (c & 3) * WBUFB;
        if (c < CH0)
            compute_chunk<0>(c, wbuf, sU, sH, sPairP, warp_m, warp_n, g, tig,
                             lane, acc);
        else
            compute_chunk<1>(c, wbuf, sU, sH, sPairP, warp_m, warp_n, g, tig,
                             lane, acc);
    }

    // ---- Epilogue 1: all 128 cols dotted with w[64:192].
#pragma unroll
    for (int rt = 0; rt < 2; ++rt) {
        int r0 = warp_m * 32 + rt * 16 + g;
        int r1 = r0 + 8;
        float s0 = 0.0f, s1 = 0.0f;
#pragma unroll
        for (int nt = 0; nt < 8; ++nt) {
            int f = 64 + warp_n * 64 + nt * 8 + 2 * tig;
            float w0 = sWv[f], w1 = sWv[f + 1];
            s0 += fmaxf(acc[rt][nt][0], 0.0f) * w0 +
                  fmaxf(acc[rt][nt][1], 0.0f) * w1;
            s1 += fmaxf(acc[rt][nt][2], 0.0f) * w0 +
                  fmaxf(acc[rt][nt][3], 0.0f) * w1;
        }
        s0 += __shfl_xor_sync(0xffffffffu, s0, 1);
        s0 += __shfl_xor_sync(0xffffffffu, s0, 2);
        s1 += __shfl_xor_sync(0xffffffffu, s1, 1);
        s1 += __shfl_xor_sync(0xffffffffu, s1, 2);
        if (tig == 0) {
            atomicAdd(&sS[r0], s0);
            atomicAdd(&sS[r1], s1);
        }
    }
    __syncthreads();

    // out[b] = bias + sum_d sS[bl*16 + d]
    if (tid < NBB) {
        float s = bias[0];
#pragma unroll
        for (int d = 0; d < DC; ++d) s += sS[tid * DC + d];
        out[b0 + tid] = s;
    }
}

// ---------------------------------------------------------------------------
extern "C" void kernel_launch(void* const* d_in, const int* in_sizes, int n_in,
                              void* d_out, int out_size) {
    (void)in_sizes; (void)n_in; (void)out_size;
    const float* x  = (const float*)d_in[0];
    const float* f0 = (const float*)d_in[1];
    const float* f1 = (const float*)d_in[2];
    const float* wv = (const float*)d_in[3];
    const float* bb = (const float*)d_in[4];
    float* out = (float*)d_out;

    cudaFuncSetAttribute(cin_kernel,
                         cudaFuncAttributeMaxDynamicSharedMemorySize,
                         SMEM_BYTES);

    fold_weights_kernel<<<(KTOT * 128 + 255) / 256, 256>>>(f0, f1);
    cin_kernel<<<512, 256, SMEM_BYTES>>>(x, wv, bb, out);
}

// round 14
// speedup vs baseline: 2.0337x; 1.0088x over previous
#include <cuda_runtime.h>
#include <cuda_fp16.h>
#include <stdint.h>

// ---------------------------------------------------------------------------
// Problem constants
// ---------------------------------------------------------------------------
#define F0C   39
#define DC    16
#define NBB   8                  // batches per CTA (8 b x 16 d = 128 GEMM rows)
#define K0R   780                // unique symmetric pairs (i<=j)
#define K0P   832                // padded to multiple of 64
#define K1C   2496               // 39*64
#define KTOT  (K0P + K1C)        // 3328
#define KCH   64                 // k per chunk (4 mma k-steps of 16)
#define NCHT  (KTOT / KCH)       // 52
#define CH0   (K0P / KCH)        // 13
#define USTR  41                 // sU row stride (floats), conflict-free
#define HSTRH 72                 // sH row stride in HALVES (144 B)

// W tile in SMEM: 64 k-rows x 128 n (fp16), row padded to 136 halves = 272 B
#define WROWB 272
#define WBUFB (64 * WROWB)       // 17408 bytes per buffer
#define WBUFW (WBUFB / 4)        // 4352 words

// SMEM layout (float-word offsets)
#define OFF_W    0               // 3 buffers x 4352 = 13056
#define OFF_U    13056           // 128 x 41 = 5248
#define OFF_H    18304           // 128 x 72 halves = 4608 words
#define OFF_PAIR 22912           // 416 words (832 packed pairs)
#define OFF_S    23328           // 128
#define OFF_WV   23456           // 192
#define SMEM_WORDS 23648
#define SMEM_BYTES (SMEM_WORDS * 4)   // 94592 -> 2 CTAs/SM

// k-permutation within a 64-chunk: fragment position kf=(ks,h2,tig,e) holds
// logical k-offset pi(kf) = tig*16 + ks*4 + h2*2 + e. This makes each
// thread's A-operand (and pair-table) loads contiguous 16B blocks.
// g_W physical row p stores logical W row (p & ~63) + pi(p & 63).
__device__ __align__(16) __half g_W[KTOT * 128];

// ---------------------------------------------------------------------------
// Helpers
// ---------------------------------------------------------------------------
__device__ __forceinline__ uint32_t pack2(float lo, float hi) {
    __half2 h = __floats2half2_rn(lo, hi);   // lo -> low 16 bits (smaller k)
    return *(uint32_t*)&h;
}

__device__ __forceinline__ uint32_t hmul2_u32(__half2 u, uint32_t hv) {
    __half2 r = __hmul2(u, *(__half2*)&hv);
    return *(uint32_t*)&r;
}

__device__ __forceinline__ void cp_async16(void* dst, const void* src) {
    unsigned sa = (unsigned)__cvta_generic_to_shared(dst);
    asm volatile("cp.async.cg.shared.global [%0], [%1], 16;\n"
                 :: "r"(sa), "l"(src));
}

__device__ __forceinline__ void ldmx4t(uint32_t& b0, uint32_t& b1,
                                       uint32_t& b2, uint32_t& b3,
                                       uint32_t addr) {
    asm volatile(
        "ldmatrix.sync.aligned.m8n8.x4.trans.shared.b16 {%0,%1,%2,%3}, [%4];"
        : "=r"(b0), "=r"(b1), "=r"(b2), "=r"(b3) : "r"(addr));
}

// D(16x8,f32) += A(16x16,f16) * B(16x8,f16)
__device__ __forceinline__ void mma_fp16(float* c, const uint32_t* a,
                                         uint32_t b0, uint32_t b1) {
    asm volatile(
        "mma.sync.aligned.m16n8k16.row.col.f32.f16.f16.f32 "
        "{%0,%1,%2,%3}, {%4,%5,%6,%7}, {%8,%9}, {%0,%1,%2,%3};\n"
        : "+f"(c[0]), "+f"(c[1]), "+f"(c[2]), "+f"(c[3])
        : "r"(a[0]), "r"(a[1]), "r"(a[2]), "r"(a[3]), "r"(b0), "r"(b1));
}

// ---------------------------------------------------------------------------
// Prologue: fold f0 pairs + append f1 -> fp16, k-major, chunk-permuted.
// ---------------------------------------------------------------------------
__global__ void fold_weights_kernel(const float* __restrict__ f0,
                                    const float* __restrict__ f1) {
    int idx = blockIdx.x * blockDim.x + threadIdx.x;
    if (idx >= KTOT * 128) return;
    int p = idx >> 7;
    int n = idx & 127;
    int kf = p & 63;
    int jperm = ((kf >> 1) & 3) * 16 + (kf >> 4) * 4 + ((kf >> 3) & 1) * 2 +
                (kf & 1);
    int k = (p & ~63) + jperm;          // logical k
    float v;
    if (k < K0P) {
        if (k < K0R) {
            int i = 0, base = 0;
            while (base + (F0C - i) <= k) { base += F0C - i; ++i; }
            int j = i + (k - base);
            v = f0[(i * F0C + j) * 128 + n];
            if (j != i) v += f0[(j * F0C + i) * 128 + n];
        } else {
            v = 0.0f;
        }
    } else {
        int k1 = k - K0P;               // i = k1>>6, j = k1&63
        v = f1[k1 * 128 + n];
    }
    g_W[idx] = __float2half_rn(v);
}

// Stage one 64x128 fp16 W chunk into a 272B-stride SMEM buffer.
__device__ __forceinline__ void stage_w(int chunk, char* dst, int tid) {
#pragma unroll
    for (int it = 0; it < 4; ++it) {
        int s = tid + it * 256;          // 1024 segments of 16B
        int row = s >> 4;
        int seg = s & 15;
        cp_async16(dst + row * WROWB + seg * 16,
                   g_W + (size_t)(chunk * 64 + row) * 128 + seg * 8);
    }
}

// ---------------------------------------------------------------------------
// One 64-k chunk. Warp tile: 32 rows x 64 cols. Two half-chunks of 2 k-steps.
// ---------------------------------------------------------------------------
template <int PHASE>
__device__ __forceinline__ void compute_chunk(
    int c, uint32_t wbuf, const float* __restrict__ sU,
    const __half* __restrict__ sH, const uint32_t* __restrict__ sPairP,
    int warp_m, int warp_n, int g, int tig, int lane, float acc[2][8][4]) {

    const int R0 = warp_m * 32 + g;
    uint32_t wbase = wbuf + (uint32_t)(lane & 15) * WROWB + warp_n * 128 +
                     ((lane >> 4) & 1) * 16;

    const float* u0  = sU + R0 * USTR;
    const float* u8  = u0 + 8 * USTR;
    const float* u16 = u0 + 16 * USTR;
    const float* u24 = u0 + 24 * USTR;

    __half2 uh0, uh8, uh16, uh24;
    const __half *h0, *h8, *h16, *h24;
    if (PHASE == 1) {
        const int iu = c - CH0;                 // one i per 64-chunk
        uh0  = __float2half2_rn(u0[iu]);
        uh8  = __float2half2_rn(u8[iu]);
        uh16 = __float2half2_rn(u16[iu]);
        uh24 = __float2half2_rn(u24[iu]);
        h0  = sH + (R0     ) * HSTRH + tig * 16;
        h8  = sH + (R0 +  8) * HSTRH + tig * 16;
        h16 = sH + (R0 + 16) * HSTRH + tig * 16;
        h24 = sH + (R0 + 24) * HSTRH + tig * 16;
    }

#pragma unroll
    for (int hs = 0; hs < 2; ++hs) {
        uint32_t a[2][2][4];   // [rowtile][ks2][areg]

        if (PHASE == 0) {
            // 4 consecutive packed-pair words per thread per half-chunk.
            uint4 P = *(const uint4*)(sPairP + c * 32 + tig * 8 + hs * 4);
            uint32_t pw[4] = {P.x, P.y, P.z, P.w};
#pragma unroll
            for (int ks2 = 0; ks2 < 2; ++ks2) {
#pragma unroll
                for (int h2 = 0; h2 < 2; ++h2) {
                    uint32_t pp = pw[ks2 * 2 + h2];
                    int j0 = pp & 255u,         i0 = (pp >> 8) & 255u;
                    int j1 = (pp >> 16) & 255u, i1 = pp >> 24;
                    a[0][ks2][h2 * 2 + 0] = pack2(u0[i0] * u0[j0],  u0[i1] * u0[j1]);
                    a[0][ks2][h2 * 2 + 1] = pack2(u8[i0] * u8[j0],  u8[i1] * u8[j1]);
                    a[1][ks2][h2 * 2 + 0] = pack2(u16[i0] * u16[j0], u16[i1] * u16[j1]);
                    a[1][ks2][h2 * 2 + 1] = pack2(u24[i0] * u24[j0], u24[i1] * u24[j1]);
                }
            }
        } else {
            // One LDS.128 per row per half-chunk: 8 contiguous halves.
            uint4 q0  = *(const uint4*)(h0  + hs * 8);
            uint4 q8  = *(const uint4*)(h8  + hs * 8);
            uint4 q16 = *(const uint4*)(h16 + hs * 8);
            uint4 q24 = *(const uint4*)(h24 + hs * 8);
            const uint32_t* w0  = (const uint32_t*)&q0;
            const uint32_t* w8  = (const uint32_t*)&q8;
            const uint32_t* w16 = (const uint32_t*)&q16;
            const uint32_t* w24 = (const uint32_t*)&q24;
#pragma unroll
            for (int ks2 = 0; ks2 < 2; ++ks2) {
#pragma unroll
                for (int h2 = 0; h2 < 2; ++h2) {
                    int w = ks2 * 2 + h2;
                    a[0][ks2][h2 * 2 + 0] = hmul2_u32(uh0,  w0[w]);
                    a[0][ks2][h2 * 2 + 1] = hmul2_u32(uh8,  w8[w]);
                    a[1][ks2][h2 * 2 + 0] = hmul2_u32(uh16, w16[w]);
                    a[1][ks2][h2 * 2 + 1] = hmul2_u32(uh24, w24[w]);
                }
            }
        }

        // B fragments + MMAs for the 2 k-steps of this half-chunk.
#pragma unroll
        for (int ks2 = 0; ks2 < 2; ++ks2) {
            uint32_t krow = (uint32_t)(hs * 2 + ks2) * (16 * WROWB);
#pragma unroll
            for (int nt2 = 0; nt2 < 4; ++nt2) {
                uint32_t b0, b1, b2, b3;
                ldmx4t(b0, b1, b2, b3, wbase + krow + nt2 * 32);
                mma_fp16(acc[0][nt2 * 2],     a[0][ks2], b0, b1);
                mma_fp16(acc[1][nt2 * 2],     a[1][ks2], b0, b1);
                mma_fp16(acc[0][nt2 * 2 + 1], a[0][ks2], b2, b3);
                mma_fp16(acc[1][nt2 * 2 + 1], a[1][ks2], b2, b3);
            }
        }
    }
}

// ---------------------------------------------------------------------------
// Main kernel: 512 CTAs x 256 threads. CTA = 8 b x 16 d = 128 GEMM rows.
// ---------------------------------------------------------------------------
__global__ void __launch_bounds__(256, 2)
cin_kernel(const float* __restrict__ x, const float* __restrict__ wv,
           const float* __restrict__ bias, float* __restrict__ out) {
    extern __shared__ __align__(16) float smem[];
    char*     sW     = (char*)(smem + OFF_W);
    float*    sU     = smem + OFF_U;
    __half*   sH     = (__half*)(smem + OFF_H);
    uint32_t* sPairP = (uint32_t*)(smem + OFF_PAIR);
    float*    sS     = smem + OFF_S;
    float*    sWv    = smem + OFF_WV;

    int tid  = threadIdx.x;
    int lane = tid & 31;
    int warp = tid >> 5;
    int g    = lane >> 2;
    int tig  = lane & 3;
    int warp_m = warp >> 1;
    int warp_n = warp & 1;
    int b0 = blockIdx.x * NBB;

    uint32_t wbase_u32 = (uint32_t)__cvta_generic_to_shared(sW);

    // Prefetch W chunk 0.
    stage_w(0, sW, tid);
    asm volatile("cp.async.commit_group;\n" ::);

    if (tid < 128) sS[tid] = 0.0f;
    if (tid < 192) sWv[tid] = wv[tid];

    // Load x tile -> sU (fp32).
    for (int idx = tid; idx < NBB * F0C * DC; idx += 256) {
        int bl  = idx / (F0C * DC);
        int rem = idx - bl * (F0C * DC);
        int i = rem >> 4;
        int d = rem & 15;
        sU[(bl * DC + d) * USTR + i] = x[(b0 + bl) * (F0C * DC) + rem];
    }

    // Packed symmetric pair table, LOGICAL k order: word e holds k=2e (lo16),
    // k=2e+1 (hi16), each (i<<8)|j. Padding k>=780 -> (0,0), W rows zero.
    for (int e = tid; e < K0P / 2; e += 256) {
        uint32_t w = 0;
#pragma unroll
        for (int h = 0; h < 2; ++h) {
            int k = 2 * e + h;
            uint32_t pk = 0;
            if (k < K0R) {
                int i = 0, base = 0;
                while (base + (F0C - i) <= k) { base += F0C - i; ++i; }
                int j = i + (k - base);
                pk = ((uint32_t)i << 8) | (uint32_t)j;
            }
            w |= pk << (16 * h);
        }
        sPairP[e] = w;
    }
    __syncthreads();

    float acc[2][8][4];
#pragma unroll
    for (int rt = 0; rt < 2; ++rt)
#pragma unroll
        for (int nt = 0; nt < 8; ++nt)
#pragma unroll
            for (int q = 0; q < 4; ++q) acc[rt][nt][q] = 0.0f;

    for (int c = 0; c < NCHT; ++c) {
        // Stage W[c+1] into buffer (c+1)%3. Its previous contents (chunk c-2)
        // were consumed by all warps before the barrier of iteration c-1.
        if (c + 1 < NCHT) {
            stage_w(c + 1, sW + ((c + 1) % 3) * WBUFB, tid);
            asm volatile("cp.async.commit_group;\n" ::);
            asm volatile("cp.async.wait_group 1;\n" ::);   // W[c] resident
        } else {
            asm volatile("cp.async.wait_group 0;\n" ::);
        }
        __syncthreads();

        if (c == CH0) {
            // ---- Epilogue 0: cols 0..63 -> h (fp16); cols 64..127 -> dot.
#pragma unroll
            for (int rt = 0; rt < 2; ++rt) {
                int r0 = warp_m * 32 + rt * 16 + g;
                int r1 = r0 + 8;
                if (warp_n == 0) {
#pragma unroll
                    for (int nt = 0; nt < 8; ++nt) {
                        int n = nt * 8 + 2 * tig;
                        *(__half2*)(sH + r0 * HSTRH + n) = __floats2half2_rn(
                            fmaxf(acc[rt][nt][0], 0.0f),
                            fmaxf(acc[rt][nt][1], 0.0f));
                        *(__half2*)(sH + r1 * HSTRH + n) = __floats2half2_rn(
                            fmaxf(acc[rt][nt][2], 0.0f),
                            fmaxf(acc[rt][nt][3], 0.0f));
                    }
                } else {
                    float s0 = 0.0f, s1 = 0.0f;
#pragma unroll
                    for (int nt = 0; nt < 8; ++nt) {
                        int f = nt * 8 + 2 * tig;
                        float w0 = sWv[f], w1 = sWv[f + 1];
                        s0 += fmaxf(acc[rt][nt][0], 0.0f) * w0 +
                              fmaxf(acc[rt][nt][1], 0.0f) * w1;
                        s1 += fmaxf(acc[rt][nt][2], 0.0f) * w0 +
                              fmaxf(acc[rt][nt][3], 0.0f) * w1;
                    }
                    s0 += __shfl_xor_sync(0xffffffffu, s0, 1);
                    s0 += __shfl_xor_sync(0xffffffffu, s0, 2);
                    s1 += __shfl_xor_sync(0xffffffffu, s1, 1);
                    s1 += __shfl_xor_sync(0xffffffffu, s1, 2);
                    if (tig == 0) {
                        atomicAdd(&sS[r0], s0);
                        atomicAdd(&sS[r1], s1);
                    }
                }
            }
#pragma unroll
            for (int rt = 0; rt < 2; ++rt)
#pragma unroll
                for (int nt = 0; nt < 8; ++nt)
#pragma unroll
                    for (int q = 0; q < 4; ++q) acc[rt][nt][q] = 0.0f;
            __syncthreads();   // sH visible to all warps before phase-1 builds
        }

        uint32_t wbuf = wbase_u32 + (c % 3) * WBUFB;
        if (c < CH0)
            compute_chunk<0>(c, wbuf, sU, sH, sPairP, warp_m, warp_n, g, tig,
                             lane, acc);
        else
            compute_chunk<1>(c, wbuf, sU, sH, sPairP, warp_m, warp_n, g, tig,
                             lane, acc);
    }

    // ---- Epilogue 1: all 128 cols dotted with w[64:192].
#pragma unroll
    for (int rt = 0; rt < 2; ++rt) {
        int r0 = warp_m * 32 + rt * 16 + g;
        int r1 = r0 + 8;
        float s0 = 0.0f, s1 = 0.0f;
#pragma unroll
        for (int nt = 0; nt < 8; ++nt) {
            int f = 64 + warp_n * 64 + nt * 8 + 2 * tig;
            float w0 = sWv[f], w1 = sWv[f + 1];
            s0 += fmaxf(acc[rt][nt][0], 0.0f) * w0 +
                  fmaxf(acc[rt][nt][1], 0.0f) * w1;
            s1 += fmaxf(acc[rt][nt][2], 0.0f) * w0 +
                  fmaxf(acc[rt][nt][3], 0.0f) * w1;
        }
        s0 += __shfl_xor_sync(0xffffffffu, s0, 1);
        s0 += __shfl_xor_sync(0xffffffffu, s0, 2);
        s1 += __shfl_xor_sync(0xffffffffu, s1, 1);
        s1 += __shfl_xor_sync(0xffffffffu, s1, 2);
        if (tig == 0) {
            atomicAdd(&sS[r0], s0);
            atomicAdd(&sS[r1], s1);
        }
    }
    __syncthreads();

    // out[b] = bias + sum_d sS[bl*16 + d]
    if (tid < NBB) {
        float s = bias[0];
#pragma unroll
        for (int d = 0; d < DC; ++d) s += sS[tid * DC + d];
        out[b0 + tid] = s;
    }
}

// ---------------------------------------------------------------------------
extern "C" void kernel_launch(void* const* d_in, const int* in_sizes, int n_in,
                              void* d_out, int out_size) {
    (void)in_sizes; (void)n_in; (void)out_size;
    const float* x  = (const float*)d_in[0];
    const float* f0 = (const float*)d_in[1];
    const float* f1 = (const float*)d_in[2];
    const float* wv = (const float*)d_in[3];
    const float* bb = (const float*)d_in[4];
    float* out = (float*)d_out;

    cudaFuncSetAttribute(cin_kernel,
                         cudaFuncAttributeMaxDynamicSharedMemorySize,
                         SMEM_BYTES);

    fold_weights_kernel<<<(KTOT * 128 + 255) / 256, 256>>>(f0, f1);
    cin_kernel<<<512, 256, SMEM_BYTES>>>(x, wv, bb, out);
}